// round 9
// baseline (speedup 1.0000x reference)
#include <cuda_runtime.h>
#include <cuda_bf16.h>
#include <math.h>
#include <stdint.h>

// Problem constants
#define N_TOKENS    16384
#define MODEL_DIM   2048
#define NUM_EXPERTS 64
#define TOPK        2
#define NK          (N_TOKENS * TOPK)      // 32768

#define BT    64                           // tokens per CTA
#define NBLK  (N_TOKENS / BT)              // 256 CTAs
#define KC    64                           // K elements per chunk (128B bf16 rows)
#define NCHUNK (MODEL_DIM / KC)            // 32
#define CHUNK_S (BT * TOPK)                // 128 slots per scatter chunk

// Output layout (concatenated float32, reference return order)
#define OFF_TOKEN  0
#define OFF_REV    (NK)
#define OFF_CW     (2 * NK)
#define OFF_SPLITS (3 * NK)
#define OFF_PROBS  (3 * NK + NUM_EXPERTS)

// Stage layout inside dynamic SMEM (per stage, 1024B aligned)
#define A_HI_OFF   0
#define A_LO_OFF   8192
#define B_HI_OFF   16384
#define B_LO_OFF   24576
#define STAGE_BYTES 32768                   // 32KB
#define SMEM_DYN   (1024 + 2 * STAGE_BYTES) // 66560

#define PREFIX_SMEM (NBLK * NUM_EXPERTS * 4)  // 64KB

// Scratch globals (no allocation allowed)
__device__ int g_flat_idx[NK];
__device__ int g_hist[NBLK][NUM_EXPERTS];
__device__ int g_offset[NBLK][NUM_EXPERTS];
__device__ __align__(16) __nv_bfloat16 g_Whi[NUM_EXPERTS * MODEL_DIM];
__device__ __align__(16) __nv_bfloat16 g_Wlo[NUM_EXPERTS * MODEL_DIM];

// ---------------------------------------------------------------------------
// Helpers (sm_80-compatible PTX only: ldmatrix + mma.sync — no tcgen05)
// ---------------------------------------------------------------------------
#define SMEM_SWIZZLE_128B(o) ((o) ^ (((o) >> 3) & 0x70u))

__device__ __forceinline__ uint32_t smem_to_u32(const void* p) {
    uint32_t a;
    asm("{ .reg .u64 t; cvta.to.shared.u64 t, %1; cvt.u32.u64 %0, t; }"
        : "=r"(a) : "l"(p));
    return a;
}

__device__ __forceinline__ void ldm_x4(uint32_t* r, uint32_t addr) {
    asm volatile("ldmatrix.sync.aligned.m8n8.x4.shared.b16 {%0,%1,%2,%3}, [%4];"
                 : "=r"(r[0]), "=r"(r[1]), "=r"(r[2]), "=r"(r[3]) : "r"(addr));
}

__device__ __forceinline__ void mma16816(float* c, const uint32_t* a,
                                         uint32_t b0, uint32_t b1) {
    asm volatile(
        "mma.sync.aligned.m16n8k16.row.col.f32.bf16.bf16.f32 "
        "{%0,%1,%2,%3}, {%4,%5,%6,%7}, {%8,%9}, {%0,%1,%2,%3};"
        : "+f"(c[0]), "+f"(c[1]), "+f"(c[2]), "+f"(c[3])
        : "r"(a[0]), "r"(a[1]), "r"(a[2]), "r"(a[3]), "r"(b0), "r"(b1));
}

// split one fp32 pair into bf16x2 hi and residual bf16x2 lo (x0 in low half)
__device__ __forceinline__ void cvt_pair(float x0, float x1,
                                         uint32_t& hi2, uint32_t& lo2) {
    asm("cvt.rn.bf16x2.f32 %0, %1, %2;" : "=r"(hi2) : "f"(x1), "f"(x0));
    float h0 = __uint_as_float(hi2 << 16);
    float h1 = __uint_as_float(hi2 & 0xffff0000u);
    float r0 = x0 - h0;
    float r1 = x1 - h1;
    asm("cvt.rn.bf16x2.f32 %0, %1, %2;" : "=r"(lo2) : "f"(r1), "f"(r0));
}

__device__ __forceinline__ void sts64(uint32_t addr, uint32_t a, uint32_t b) {
    asm volatile("st.shared.v2.b32 [%0], {%1, %2};"
                 :: "r"(addr), "r"(a), "r"(b) : "memory");
}
__device__ __forceinline__ void sts128(uint32_t addr, uint4 v) {
    asm volatile("st.shared.v4.b32 [%0], {%1, %2, %3, %4};"
                 :: "r"(addr), "r"(v.x), "r"(v.y), "r"(v.z), "r"(v.w) : "memory");
}

// ---------------------------------------------------------------------------
// Kernel 0: convert W fp32 -> bf16 hi/lo (64 x 2048, one float4 per thread)
// ---------------------------------------------------------------------------
__global__ __launch_bounds__(256) void wconv_kernel(const float* __restrict__ W)
{
    int idx = blockIdx.x * 256 + threadIdx.x;      // 0 .. 32767
    float4 v = *(const float4*)(W + (size_t)idx * 4);
    uint32_t h0, l0, h1, l1;
    cvt_pair(v.x, v.y, h0, l0);
    cvt_pair(v.z, v.w, h1, l1);
    ((uint2*)g_Whi)[idx] = make_uint2(h0, h1);
    ((uint2*)g_Wlo)[idx] = make_uint2(l0, l1);
}

// ---------------------------------------------------------------------------
// Kernel 1: HMMA split-bf16 gate GEMM + softmax + top-2 + chunk hist
// BT=64 tokens, 128 threads, 4 warps (32x32 tiles), 2 CTAs per SM.
// ---------------------------------------------------------------------------
__global__ __launch_bounds__(128, 2) void gate_kernel(
    const float* __restrict__ X,    // [N_TOKENS, MODEL_DIM]
    float* __restrict__ out)
{
    extern __shared__ char dsm[];
    __shared__ float logits[BT][NUM_EXPERTS + 1];
    __shared__ int s_hist[NUM_EXPERTS];

    const int tid  = threadIdx.x;
    const int lane = tid & 31;
    const int w    = tid >> 5;
    const int b    = blockIdx.x;
    const int t0   = b * BT;

    uint32_t smem_raw = smem_to_u32(dsm);
    const uint32_t tile0 = (smem_raw + 1023) & ~1023u;

    if (tid < NUM_EXPERTS) s_hist[tid] = 0;

    // Warp tile: 32 tokens x 32 experts (4 warps cover 64x64)
    const int wm = (w & 1) * 32;        // token rows
    const int wn = (w >> 1) * 32;       // expert cols

    // ldmatrix per-lane addressing
    const uint32_t a_row  = (uint32_t)(lane & 15);
    const uint32_t a_koff = (uint32_t)((lane >> 4) << 4);
    const uint32_t b_row  = (uint32_t)((lane & 7) + ((lane & 16) ? 8 : 0));
    const uint32_t b_koff = (uint32_t)((lane & 8) ? 16 : 0);

    float acc[2][4][4];
#pragma unroll
    for (int mi = 0; mi < 2; mi++)
#pragma unroll
        for (int j = 0; j < 4; j++)
#pragma unroll
            for (int q = 0; q < 4; q++) acc[mi][j][q] = 0.0f;

    // Prefetch registers: A = 64 rows x 16 float4 / 128 thr = 8 each
    //                     B = 64 rows x 8 uint4 / 128 thr = 4 each (hi & lo)
    float4 pa[8];
    uint4  pbh[4], pbl[4];

    {
        const int k0 = 0;
#pragma unroll
        for (int l = 0; l < 8; l++) {
            int i = l * 128 + tid;
            int row = i >> 4, q = i & 15;
            pa[l] = *(const float4*)(X + (size_t)(t0 + row) * MODEL_DIM + k0 + q * 4);
        }
#pragma unroll
        for (int l = 0; l < 4; l++) {
            int i = l * 128 + tid;
            int row = i >> 3, u = i & 7;
            pbh[l] = *(const uint4*)((const char*)g_Whi + ((size_t)row * MODEL_DIM + k0) * 2 + u * 16);
            pbl[l] = *(const uint4*)((const char*)g_Wlo + ((size_t)row * MODEL_DIM + k0) * 2 + u * 16);
        }
    }

    for (int c = 0; c < NCHUNK; c++) {
        const uint32_t sb = tile0 + (uint32_t)(c & 1) * STAGE_BYTES;

        // convert + store prefetched chunk c into SMEM stage
#pragma unroll
        for (int l = 0; l < 8; l++) {
            int i = l * 128 + tid;
            int row = i >> 4, q = i & 15;
            uint32_t h0, l0v, h1, l1v;
            cvt_pair(pa[l].x, pa[l].y, h0, l0v);
            cvt_pair(pa[l].z, pa[l].w, h1, l1v);
            uint32_t off = SMEM_SWIZZLE_128B((uint32_t)(row * 128 + q * 8));
            sts64(sb + A_HI_OFF + off, h0, h1);
            sts64(sb + A_LO_OFF + off, l0v, l1v);
        }
#pragma unroll
        for (int l = 0; l < 4; l++) {
            int i = l * 128 + tid;
            int row = i >> 3, u = i & 7;
            uint32_t off = SMEM_SWIZZLE_128B((uint32_t)(row * 128 + u * 16));
            sts128(sb + B_HI_OFF + off, pbh[l]);
            sts128(sb + B_LO_OFF + off, pbl[l]);
        }

        // issue prefetch for chunk c+1 (overlaps with MMA below)
        if (c + 1 < NCHUNK) {
            const int k0 = (c + 1) * KC;
#pragma unroll
            for (int l = 0; l < 8; l++) {
                int i = l * 128 + tid;
                int row = i >> 4, q = i & 15;
                pa[l] = *(const float4*)(X + (size_t)(t0 + row) * MODEL_DIM + k0 + q * 4);
            }
#pragma unroll
            for (int l = 0; l < 4; l++) {
                int i = l * 128 + tid;
                int row = i >> 3, u = i & 7;
                pbh[l] = *(const uint4*)((const char*)g_Whi + ((size_t)row * MODEL_DIM + k0) * 2 + u * 16);
                pbl[l] = *(const uint4*)((const char*)g_Wlo + ((size_t)row * MODEL_DIM + k0) * 2 + u * 16);
            }
        }
        __syncthreads();

        // compute: 4 k-steps of k16 over this chunk
#pragma unroll
        for (int kk = 0; kk < 4; kk++) {
            uint32_t ah[2][4], al[2][4];
#pragma unroll
            for (int mi = 0; mi < 2; mi++) {
                uint32_t ro = (uint32_t)((wm + 16 * mi + a_row) * 128) + kk * 32 + a_koff;
                uint32_t sw = SMEM_SWIZZLE_128B(ro);
                ldm_x4(ah[mi], sb + A_HI_OFF + sw);
                ldm_x4(al[mi], sb + A_LO_OFF + sw);
            }
            uint32_t bh[2][4], bl[2][4];
#pragma unroll
            for (int bi = 0; bi < 2; bi++) {
                uint32_t ro = (uint32_t)((wn + 16 * bi + b_row) * 128) + kk * 32 + b_koff;
                uint32_t sw = SMEM_SWIZZLE_128B(ro);
                ldm_x4(bh[bi], sb + B_HI_OFF + sw);
                ldm_x4(bl[bi], sb + B_LO_OFF + sw);
            }
#pragma unroll
            for (int mi = 0; mi < 2; mi++) {
#pragma unroll
                for (int j = 0; j < 4; j++) {
                    const int bi = j >> 1, sel = (j & 1) * 2;
                    mma16816(acc[mi][j], ah[mi], bh[bi][sel], bh[bi][sel + 1]);
                    mma16816(acc[mi][j], ah[mi], bl[bi][sel], bl[bi][sel + 1]);
                    mma16816(acc[mi][j], al[mi], bh[bi][sel], bh[bi][sel + 1]);
                }
            }
        }
        __syncthreads();
    }

    // Dump accumulators -> SMEM logits [64][65]
#pragma unroll
    for (int mi = 0; mi < 2; mi++) {
        int r0 = wm + 16 * mi + (lane >> 2);
#pragma unroll
        for (int j = 0; j < 4; j++) {
            int col = wn + j * 8 + 2 * (lane & 3);
            logits[r0][col]         = acc[mi][j][0];
            logits[r0][col + 1]     = acc[mi][j][1];
            logits[r0 + 8][col]     = acc[mi][j][2];
            logits[r0 + 8][col + 1] = acc[mi][j][3];
        }
    }
    __syncthreads();

    // Phase 2: one thread per token (first 64 threads)
    if (tid < BT) {
        float* row = logits[tid];
        const int token = t0 + tid;

        float m1 = -INFINITY; int e1 = 0;
#pragma unroll
        for (int e = 0; e < NUM_EXPERTS; e++) {
            float v = row[e];
            if (v > m1) { m1 = v; e1 = e; }
        }
        float m2 = -INFINITY; int e2 = 0;
#pragma unroll
        for (int e = 0; e < NUM_EXPERTS; e++) {
            float v = row[e];
            if (e != e1 && v > m2) { m2 = v; e2 = e; }
        }

        float s = 0.0f;
#pragma unroll
        for (int e = 0; e < NUM_EXPERTS; e++) {
            float ex = expf(row[e] - m1);
            row[e] = ex;
            s += ex;
        }
        float inv = 1.0f / s;
#pragma unroll
        for (int e = 0; e < NUM_EXPERTS; e++) row[e] *= inv;

        float p1 = row[e1];
        float p2 = row[e2];
        float r  = expf(p2 - p1);           // combine = softmax([p1,p2])
        float c1 = 1.0f / (1.0f + r);
        float c2 = r * c1;

        int gi = 2 * token;
        g_flat_idx[gi]     = e1;
        g_flat_idx[gi + 1] = e2;
        out[OFF_CW + gi]     = c1;
        out[OFF_CW + gi + 1] = c2;

        atomicAdd(&s_hist[e1], 1);
        atomicAdd(&s_hist[e2], 1);
    }
    __syncthreads();

    // Coalesced probs writeout: 64 x 64 floats
    for (int i = tid; i < BT * NUM_EXPERTS; i += 128) {
        out[OFF_PROBS + (size_t)t0 * NUM_EXPERTS + i] = logits[i >> 6][i & 63];
    }
    if (tid < NUM_EXPERTS) g_hist[b][tid] = s_hist[tid];
}

// ---------------------------------------------------------------------------
// Kernel 2: per-expert chunk-prefix + expert base offsets + input_splits
// ---------------------------------------------------------------------------
__global__ __launch_bounds__(256) void prefix_kernel(float* __restrict__ out)
{
    extern __shared__ int sh[];              // NBLK*NUM_EXPERTS = 64KB
    __shared__ int s_cnt[NUM_EXPERTS];
    __shared__ int s_base[NUM_EXPERTS];
    const int tid = threadIdx.x;

    const int4* src = (const int4*)g_hist;
    int4* dst = (int4*)sh;
    for (int i = tid; i < NBLK * NUM_EXPERTS / 4; i += 256) dst[i] = src[i];
    __syncthreads();

    if (tid < NUM_EXPERTS) {
        int run = 0;
#pragma unroll 8
        for (int c = 0; c < NBLK; c++) run += sh[c * NUM_EXPERTS + tid];
        s_cnt[tid] = run;
    }
    __syncthreads();
    if (tid == 0) {
        int base = 0;
        for (int i = 0; i < NUM_EXPERTS; i++) { s_base[i] = base; base += s_cnt[i]; }
    }
    __syncthreads();
    if (tid < NUM_EXPERTS) {
        out[OFF_SPLITS + tid] = (float)s_cnt[tid];
        int run = s_base[tid];
#pragma unroll 8
        for (int c = 0; c < NBLK; c++) {
            g_offset[c][tid] = run;
            run += sh[c * NUM_EXPERTS + tid];
        }
    }
}

// ---------------------------------------------------------------------------
// Kernel 3: stable scatter via match_any + per-warp histograms
// 256 blocks x 128 threads (4 warps), chunk = 128 slots
// ---------------------------------------------------------------------------
__global__ __launch_bounds__(CHUNK_S) void scatter_kernel(float* __restrict__ out)
{
    __shared__ int whist[4][NUM_EXPERTS];
    const int tid  = threadIdx.x;
    const int lane = tid & 31;
    const int w    = tid >> 5;
    const int b    = blockIdx.x;
    const int gi   = b * CHUNK_S + tid;

    for (int i = tid; i < 4 * NUM_EXPERTS; i += CHUNK_S) ((int*)whist)[i] = 0;
    __syncthreads();

    const int me = g_flat_idx[gi];
    unsigned mask = __match_any_sync(0xffffffffu, me);
    int before = __popc(mask & ((1u << lane) - 1u));
    if (before == 0) whist[w][me] = __popc(mask);   // lowest matching lane = leader
    __syncthreads();

    int r = before;
#pragma unroll
    for (int ww = 0; ww < 4; ww++)
        if (ww < w) r += whist[ww][me];

    const int pos = g_offset[b][me] + r;
    out[OFF_TOKEN + pos] = (float)(gi >> 1);   // token index
    out[OFF_REV + gi]    = (float)pos;         // reversed ordering
}

// ---------------------------------------------------------------------------
extern "C" void kernel_launch(void* const* d_in, const int* in_sizes, int n_in,
                              void* d_out, int out_size)
{
    const float* X = (const float*)d_in[0];   // inputs [16384, 2048]
    const float* W = (const float*)d_in[1];   // wg_weight [64, 2048]
    float* out = (float*)d_out;

    cudaFuncSetAttribute(gate_kernel,
                         cudaFuncAttributeMaxDynamicSharedMemorySize, SMEM_DYN);
    cudaFuncSetAttribute(prefix_kernel,
                         cudaFuncAttributeMaxDynamicSharedMemorySize, PREFIX_SMEM);

    wconv_kernel<<<128, 256>>>(W);
    gate_kernel<<<NBLK, 128, SMEM_DYN>>>(X, out);
    prefix_kernel<<<1, 256, PREFIX_SMEM>>>(out);
    scatter_kernel<<<NBLK, CHUNK_S>>>(out);
}

// round 10
// speedup vs baseline: 1.1281x; 1.1281x over previous
#include <cuda_runtime.h>
#include <cuda_bf16.h>
#include <math.h>
#include <stdint.h>

// Problem constants
#define N_TOKENS    16384
#define MODEL_DIM   2048
#define NUM_EXPERTS 64
#define TOPK        2
#define NK          (N_TOKENS * TOPK)      // 32768

#define BT    128                          // tokens per CTA
#define KSPLIT 2
#define KHALF (MODEL_DIM / KSPLIT)         // 1024
#define KC    64                           // K elements per chunk
#define NCHUNK (KHALF / KC)                // 16 chunks per CTA
#define NGATE (N_TOKENS / BT * KSPLIT)     // 256 gate CTAs
#define HBLK  (N_TOKENS / BT)              // 128 hist chunks
#define CHUNK (BT * TOPK)                  // 256 slots per hist chunk

// Output layout (concatenated float32, reference return order)
#define OFF_TOKEN  0
#define OFF_REV    (NK)
#define OFF_CW     (2 * NK)
#define OFF_SPLITS (3 * NK)
#define OFF_PROBS  (3 * NK + NUM_EXPERTS)

// Stage layout inside dynamic SMEM (per stage, 1024B aligned)
#define A_HI_OFF   0
#define A_LO_OFF   16384
#define B_HI_OFF   32768
#define B_LO_OFF   40960
#define STAGE_BYTES 49152                   // 48KB
#define SMEM_DYN   (1024 + 2 * STAGE_BYTES) // 99328 -> 2 CTAs/SM

// Scratch globals (no allocation allowed)
__device__ int g_flat_idx[NK];
__device__ int g_hist[HBLK][NUM_EXPERTS];
__device__ __align__(16) float g_part[KSPLIT][N_TOKENS * NUM_EXPERTS]; // 8MB
__device__ __align__(16) __nv_bfloat16 g_Whi[NUM_EXPERTS * MODEL_DIM];
__device__ __align__(16) __nv_bfloat16 g_Wlo[NUM_EXPERTS * MODEL_DIM];

// ---------------------------------------------------------------------------
// Helpers (sm_80-compatible PTX only)
// ---------------------------------------------------------------------------
#define SMEM_SWIZZLE_128B(o) ((o) ^ (((o) >> 3) & 0x70u))

__device__ __forceinline__ uint32_t smem_to_u32(const void* p) {
    uint32_t a;
    asm("{ .reg .u64 t; cvta.to.shared.u64 t, %1; cvt.u32.u64 %0, t; }"
        : "=r"(a) : "l"(p));
    return a;
}

__device__ __forceinline__ void ldm_x4(uint32_t* r, uint32_t addr) {
    asm volatile("ldmatrix.sync.aligned.m8n8.x4.shared.b16 {%0,%1,%2,%3}, [%4];"
                 : "=r"(r[0]), "=r"(r[1]), "=r"(r[2]), "=r"(r[3]) : "r"(addr));
}

__device__ __forceinline__ void mma16816(float* c, const uint32_t* a,
                                         uint32_t b0, uint32_t b1) {
    asm volatile(
        "mma.sync.aligned.m16n8k16.row.col.f32.bf16.bf16.f32 "
        "{%0,%1,%2,%3}, {%4,%5,%6,%7}, {%8,%9}, {%0,%1,%2,%3};"
        : "+f"(c[0]), "+f"(c[1]), "+f"(c[2]), "+f"(c[3])
        : "r"(a[0]), "r"(a[1]), "r"(a[2]), "r"(a[3]), "r"(b0), "r"(b1));
}

// split one fp32 pair into bf16x2 hi and residual bf16x2 lo (x0 in low half)
__device__ __forceinline__ void cvt_pair(float x0, float x1,
                                         uint32_t& hi2, uint32_t& lo2) {
    asm("cvt.rn.bf16x2.f32 %0, %1, %2;" : "=r"(hi2) : "f"(x1), "f"(x0));
    float h0 = __uint_as_float(hi2 << 16);
    float h1 = __uint_as_float(hi2 & 0xffff0000u);
    float r0 = x0 - h0;
    float r1 = x1 - h1;
    asm("cvt.rn.bf16x2.f32 %0, %1, %2;" : "=r"(lo2) : "f"(r1), "f"(r0));
}

__device__ __forceinline__ void sts64(uint32_t addr, uint32_t a, uint32_t b) {
    asm volatile("st.shared.v2.b32 [%0], {%1, %2};"
                 :: "r"(addr), "r"(a), "r"(b) : "memory");
}

#define CP_ASYNC16(dst, src) \
    asm volatile("cp.async.cg.shared.global [%0], [%1], 16;" \
                 :: "r"(dst), "l"(src) : "memory")
#define CP_COMMIT() asm volatile("cp.async.commit_group;" ::: "memory")
#define CP_WAIT1()  asm volatile("cp.async.wait_group 1;" ::: "memory")
#define CP_WAIT0()  asm volatile("cp.async.wait_group 0;" ::: "memory")

// ---------------------------------------------------------------------------
// Kernel 0: convert W fp32 -> bf16 hi/lo
// ---------------------------------------------------------------------------
__global__ __launch_bounds__(256) void wconv_kernel(const float* __restrict__ W)
{
    int idx = blockIdx.x * 256 + threadIdx.x;      // 0 .. 32767
    float4 v = *(const float4*)(W + (size_t)idx * 4);
    uint32_t h0, l0, h1, l1;
    cvt_pair(v.x, v.y, h0, l0);
    cvt_pair(v.z, v.w, h1, l1);
    ((uint2*)g_Whi)[idx] = make_uint2(h0, h1);
    ((uint2*)g_Wlo)[idx] = make_uint2(l0, l1);
}

// ---------------------------------------------------------------------------
// Kernel 1: HMMA split-bf16 gate GEMM, K-split x2 -> fp32 partials in gmem
// 256 threads, 8 warps (32x32 tiles), 2 CTAs/SM.
// ---------------------------------------------------------------------------
__global__ __launch_bounds__(256, 2) void gate_kernel(
    const float* __restrict__ X)    // [N_TOKENS, MODEL_DIM]
{
    extern __shared__ char dsm[];

    const int tid  = threadIdx.x;
    const int lane = tid & 31;
    const int w    = tid >> 5;
    const int b    = blockIdx.x >> 1;
    const int ks   = blockIdx.x & 1;
    const int t0   = b * BT;
    const int kbase = ks * KHALF;

    uint32_t smem_raw = smem_to_u32(dsm);
    const uint32_t tile0 = (smem_raw + 1023) & ~1023u;

    // Warp tile: 32 tokens x 32 experts
    const int wm = (w & 3) * 32;        // token rows
    const int wn = (w >> 2) * 32;       // expert cols

    const uint32_t a_row  = (uint32_t)(lane & 15);
    const uint32_t a_koff = (uint32_t)((lane >> 4) << 4);
    const uint32_t b_row  = (uint32_t)((lane & 7) + ((lane & 16) ? 8 : 0));
    const uint32_t b_koff = (uint32_t)((lane & 8) ? 16 : 0);

    float acc[2][4][4];
#pragma unroll
    for (int mi = 0; mi < 2; mi++)
#pragma unroll
        for (int j = 0; j < 4; j++)
#pragma unroll
            for (int q = 0; q < 4; q++) acc[mi][j][q] = 0.0f;

    // A prefetch registers: 128 rows x 16 float4 / 256 thr = 8 each
    float4 pa[8];

    // B cp.async issue helper (4 x 16B per thread per chunk)
    const int brow = tid >> 3;          // 0..31 (x2 via l)
    const int bu   = tid & 7;

    // prologue: LDG A(0), cp.async B(0) into stage 0
    {
        const int k0 = kbase;
#pragma unroll
        for (int l = 0; l < 8; l++) {
            int i = l * 256 + tid;
            int row = i >> 4, q = i & 15;
            pa[l] = *(const float4*)(X + (size_t)(t0 + row) * MODEL_DIM + k0 + q * 4);
        }
#pragma unroll
        for (int l = 0; l < 2; l++) {
            int row = brow + l * 32;
            uint32_t off = SMEM_SWIZZLE_128B((uint32_t)(row * 128 + bu * 16));
            CP_ASYNC16(tile0 + B_HI_OFF + off,
                       (const char*)g_Whi + ((size_t)row * MODEL_DIM + k0) * 2 + bu * 16);
            CP_ASYNC16(tile0 + B_LO_OFF + off,
                       (const char*)g_Wlo + ((size_t)row * MODEL_DIM + k0) * 2 + bu * 16);
        }
        CP_COMMIT();
    }

    for (int c = 0; c < NCHUNK; c++) {
        const uint32_t sb = tile0 + (uint32_t)(c & 1) * STAGE_BYTES;
        const uint32_t sbn = tile0 + (uint32_t)((c + 1) & 1) * STAGE_BYTES;

        // convert + store prefetched A chunk c into its stage
#pragma unroll
        for (int l = 0; l < 8; l++) {
            int i = l * 256 + tid;
            int row = i >> 4, q = i & 15;
            uint32_t h0, l0v, h1, l1v;
            cvt_pair(pa[l].x, pa[l].y, h0, l0v);
            cvt_pair(pa[l].z, pa[l].w, h1, l1v);
            uint32_t off = SMEM_SWIZZLE_128B((uint32_t)(row * 128 + q * 8));
            sts64(sb + A_HI_OFF + off, h0, h1);
            sts64(sb + A_LO_OFF + off, l0v, l1v);
        }

        // issue A LDG + B cp.async for chunk c+1 (lands during MMA below)
        if (c + 1 < NCHUNK) {
            const int k0 = kbase + (c + 1) * KC;
#pragma unroll
            for (int l = 0; l < 8; l++) {
                int i = l * 256 + tid;
                int row = i >> 4, q = i & 15;
                pa[l] = *(const float4*)(X + (size_t)(t0 + row) * MODEL_DIM + k0 + q * 4);
            }
#pragma unroll
            for (int l = 0; l < 2; l++) {
                int row = brow + l * 32;
                uint32_t off = SMEM_SWIZZLE_128B((uint32_t)(row * 128 + bu * 16));
                CP_ASYNC16(sbn + B_HI_OFF + off,
                           (const char*)g_Whi + ((size_t)row * MODEL_DIM + k0) * 2 + bu * 16);
                CP_ASYNC16(sbn + B_LO_OFF + off,
                           (const char*)g_Wlo + ((size_t)row * MODEL_DIM + k0) * 2 + bu * 16);
            }
            CP_COMMIT();
            CP_WAIT1();       // chunk c's B group is complete
        } else {
            CP_WAIT0();
        }
        __syncthreads();

        // compute: 4 k-steps of k16 over this chunk
#pragma unroll
        for (int kk = 0; kk < 4; kk++) {
            uint32_t ah[2][4], al[2][4];
#pragma unroll
            for (int mi = 0; mi < 2; mi++) {
                uint32_t ro = (uint32_t)((wm + 16 * mi + a_row) * 128) + kk * 32 + a_koff;
                uint32_t sw = SMEM_SWIZZLE_128B(ro);
                ldm_x4(ah[mi], sb + A_HI_OFF + sw);
                ldm_x4(al[mi], sb + A_LO_OFF + sw);
            }
            uint32_t bh[2][4], bl[2][4];
#pragma unroll
            for (int bi = 0; bi < 2; bi++) {
                uint32_t ro = (uint32_t)((wn + 16 * bi + b_row) * 128) + kk * 32 + b_koff;
                uint32_t sw = SMEM_SWIZZLE_128B(ro);
                ldm_x4(bh[bi], sb + B_HI_OFF + sw);
                ldm_x4(bl[bi], sb + B_LO_OFF + sw);
            }
#pragma unroll
            for (int mi = 0; mi < 2; mi++) {
#pragma unroll
                for (int j = 0; j < 4; j++) {
                    const int bi = j >> 1, sel = (j & 1) * 2;
                    mma16816(acc[mi][j], ah[mi], bh[bi][sel], bh[bi][sel + 1]);
                    mma16816(acc[mi][j], ah[mi], bl[bi][sel], bl[bi][sel + 1]);
                    mma16816(acc[mi][j], al[mi], bh[bi][sel], bh[bi][sel + 1]);
                }
            }
        }
        __syncthreads();
    }

    // Write fp32 partial logits to gmem
    float* gp = g_part[ks];
#pragma unroll
    for (int mi = 0; mi < 2; mi++) {
        int r0 = wm + 16 * mi + (lane >> 2);
#pragma unroll
        for (int j = 0; j < 4; j++) {
            int col = wn + j * 8 + 2 * (lane & 3);
            *(float2*)(gp + (size_t)(t0 + r0) * NUM_EXPERTS + col) =
                make_float2(acc[mi][j][0], acc[mi][j][1]);
            *(float2*)(gp + (size_t)(t0 + r0 + 8) * NUM_EXPERTS + col) =
                make_float2(acc[mi][j][2], acc[mi][j][3]);
        }
    }
}

// ---------------------------------------------------------------------------
// Kernel 2: sum partials + softmax + top-2 + combine weights + hist
// 128 blocks x 128 threads, one token per thread
// ---------------------------------------------------------------------------
__global__ __launch_bounds__(128) void finish_kernel(float* __restrict__ out)
{
    __shared__ float sm[BT][NUM_EXPERTS + 1];
    __shared__ int s_hist[NUM_EXPERTS];
    const int tid = threadIdx.x;
    const int b   = blockIdx.x;
    const int t0  = b * BT;

    if (tid < NUM_EXPERTS) s_hist[tid] = 0;

    // coalesced load + sum of the two partial halves
    const float* p0 = g_part[0] + (size_t)t0 * NUM_EXPERTS;
    const float* p1 = g_part[1] + (size_t)t0 * NUM_EXPERTS;
    for (int i = tid; i < BT * NUM_EXPERTS; i += 128)
        sm[i >> 6][i & 63] = p0[i] + p1[i];
    __syncthreads();

    {
        float* row = sm[tid];
        const int token = t0 + tid;

        float m1 = -INFINITY; int e1 = 0;
#pragma unroll
        for (int e = 0; e < NUM_EXPERTS; e++) {
            float v = row[e];
            if (v > m1) { m1 = v; e1 = e; }
        }
        float m2 = -INFINITY; int e2 = 0;
#pragma unroll
        for (int e = 0; e < NUM_EXPERTS; e++) {
            float v = row[e];
            if (e != e1 && v > m2) { m2 = v; e2 = e; }
        }

        float s = 0.0f;
#pragma unroll
        for (int e = 0; e < NUM_EXPERTS; e++) {
            float ex = expf(row[e] - m1);
            row[e] = ex;
            s += ex;
        }
        float inv = 1.0f / s;
#pragma unroll
        for (int e = 0; e < NUM_EXPERTS; e++) row[e] *= inv;

        float p1v = row[e1];
        float p2v = row[e2];
        float r  = expf(p2v - p1v);         // combine = softmax([p1,p2])
        float c1 = 1.0f / (1.0f + r);
        float c2 = r * c1;

        int gi = 2 * token;
        g_flat_idx[gi]     = e1;
        g_flat_idx[gi + 1] = e2;
        out[OFF_CW + gi]     = c1;
        out[OFF_CW + gi + 1] = c2;

        atomicAdd(&s_hist[e1], 1);
        atomicAdd(&s_hist[e2], 1);
    }
    __syncthreads();

    // coalesced probs writeout
    for (int i = tid; i < BT * NUM_EXPERTS; i += 128)
        out[OFF_PROBS + (size_t)t0 * NUM_EXPERTS + i] = sm[i >> 6][i & 63];

    if (tid < NUM_EXPERTS) g_hist[b][tid] = s_hist[tid];
}

// ---------------------------------------------------------------------------
// Kernel 3: stable scatter; prefix computed per-block from the full histogram
// 128 blocks x 256 threads (8 warps), chunk = 256 slots
// ---------------------------------------------------------------------------
__global__ __launch_bounds__(CHUNK) void scatter_kernel(float* __restrict__ out)
{
    __shared__ int sh[HBLK * NUM_EXPERTS];   // 32KB
    __shared__ int whist[8][NUM_EXPERTS];
    __shared__ int s_cnt[NUM_EXPERTS];
    __shared__ int s_off[NUM_EXPERTS];
    __shared__ int s_base[NUM_EXPERTS];
    const int tid  = threadIdx.x;
    const int lane = tid & 31;
    const int w    = tid >> 5;
    const int b    = blockIdx.x;
    const int gi   = b * CHUNK + tid;

    // stage full histogram (coalesced)
    {
        const int4* src = (const int4*)g_hist;
        int4* dst = (int4*)sh;
        for (int i = tid; i < HBLK * NUM_EXPERTS / 4; i += CHUNK) dst[i] = src[i];
    }
    for (int i = tid; i < 8 * NUM_EXPERTS; i += CHUNK) ((int*)whist)[i] = 0;
    __syncthreads();

    if (tid < NUM_EXPERTS) {
        int cnt = 0, off = 0;
#pragma unroll 8
        for (int c = 0; c < HBLK; c++) {
            int h = sh[c * NUM_EXPERTS + tid];
            cnt += h;
            off += (c < b) ? h : 0;
        }
        s_cnt[tid] = cnt;
        s_off[tid] = off;
        if (b == 0) out[OFF_SPLITS + tid] = (float)cnt;
    }
    __syncthreads();
    if (tid == 0) {
        int base = 0;
        for (int e = 0; e < NUM_EXPERTS; e++) { s_base[e] = base; base += s_cnt[e]; }
    }

    const int me = g_flat_idx[gi];
    unsigned mask = __match_any_sync(0xffffffffu, me);
    int before = __popc(mask & ((1u << lane) - 1u));
    if (before == 0) whist[w][me] = __popc(mask);
    __syncthreads();

    int r = before;
#pragma unroll
    for (int ww = 0; ww < 8; ww++)
        if (ww < w) r += whist[ww][me];

    const int pos = s_base[me] + s_off[me] + r;
    out[OFF_TOKEN + pos] = (float)(gi >> 1);   // token index
    out[OFF_REV + gi]    = (float)pos;         // reversed ordering
}

// ---------------------------------------------------------------------------
extern "C" void kernel_launch(void* const* d_in, const int* in_sizes, int n_in,
                              void* d_out, int out_size)
{
    const float* X = (const float*)d_in[0];   // inputs [16384, 2048]
    const float* W = (const float*)d_in[1];   // wg_weight [64, 2048]
    float* out = (float*)d_out;

    cudaFuncSetAttribute(gate_kernel,
                         cudaFuncAttributeMaxDynamicSharedMemorySize, SMEM_DYN);

    wconv_kernel<<<128, 256>>>(W);
    gate_kernel<<<NGATE, 256, SMEM_DYN>>>(X);
    finish_kernel<<<HBLK, 128>>>(out);
    scatter_kernel<<<HBLK, CHUNK>>>(out);
}

// round 13
// speedup vs baseline: 1.2100x; 1.0727x over previous
#include <cuda_runtime.h>
#include <cuda_bf16.h>
#include <math.h>
#include <stdint.h>

// Problem constants
#define N_TOKENS    16384
#define MODEL_DIM   2048
#define NUM_EXPERTS 64
#define TOPK        2
#define NK          (N_TOKENS * TOPK)      // 32768

#define BT    128                          // tokens per CTA
#define KSPLIT 2
#define KHALF (MODEL_DIM / KSPLIT)         // 1024
#define KC    64                           // K elements per chunk
#define NCHUNK (KHALF / KC)                // 16 chunks per CTA
#define NGATE (N_TOKENS / BT * KSPLIT)     // 256 gate CTAs
#define HBLK  (N_TOKENS / BT)              // 128 hist chunks
#define CHUNK (BT * TOPK)                  // 256 slots per hist chunk

// Output layout (concatenated float32, reference return order)
#define OFF_TOKEN  0
#define OFF_REV    (NK)
#define OFF_CW     (2 * NK)
#define OFF_SPLITS (3 * NK)
#define OFF_PROBS  (3 * NK + NUM_EXPERTS)

// Stage layout inside dynamic SMEM (per stage, 1024B aligned)
#define A_HI_OFF   0
#define A_LO_OFF   16384
#define B_HI_OFF   32768
#define B_LO_OFF   40960
#define STAGE_BYTES 49152                   // 48KB
#define SMEM_DYN   (1024 + 2 * STAGE_BYTES) // 99328 -> 2 CTAs/SM

// Scratch globals (no allocation allowed)
__device__ int g_flat_idx[NK];
__device__ int g_hist[HBLK][NUM_EXPERTS];
__device__ int g_offset[HBLK][NUM_EXPERTS];
__device__ __align__(16) float g_part[KSPLIT][N_TOKENS * NUM_EXPERTS]; // 8MB
__device__ __align__(16) __nv_bfloat16 g_Whi[NUM_EXPERTS * MODEL_DIM];
__device__ __align__(16) __nv_bfloat16 g_Wlo[NUM_EXPERTS * MODEL_DIM];

// ---------------------------------------------------------------------------
// Helpers (sm_80-compatible PTX only)
// ---------------------------------------------------------------------------
#define SMEM_SWIZZLE_128B(o) ((o) ^ (((o) >> 3) & 0x70u))

__device__ __forceinline__ uint32_t smem_to_u32(const void* p) {
    uint32_t a;
    asm("{ .reg .u64 t; cvta.to.shared.u64 t, %1; cvt.u32.u64 %0, t; }"
        : "=r"(a) : "l"(p));
    return a;
}

__device__ __forceinline__ void ldm_x4(uint32_t* r, uint32_t addr) {
    asm volatile("ldmatrix.sync.aligned.m8n8.x4.shared.b16 {%0,%1,%2,%3}, [%4];"
                 : "=r"(r[0]), "=r"(r[1]), "=r"(r[2]), "=r"(r[3]) : "r"(addr));
}

__device__ __forceinline__ void mma16816(float* c, const uint32_t* a,
                                         uint32_t b0, uint32_t b1) {
    asm volatile(
        "mma.sync.aligned.m16n8k16.row.col.f32.bf16.bf16.f32 "
        "{%0,%1,%2,%3}, {%4,%5,%6,%7}, {%8,%9}, {%0,%1,%2,%3};"
        : "+f"(c[0]), "+f"(c[1]), "+f"(c[2]), "+f"(c[3])
        : "r"(a[0]), "r"(a[1]), "r"(a[2]), "r"(a[3]), "r"(b0), "r"(b1));
}

// split one fp32 pair into bf16x2 hi and residual bf16x2 lo (x0 in low half)
__device__ __forceinline__ void cvt_pair(float x0, float x1,
                                         uint32_t& hi2, uint32_t& lo2) {
    asm("cvt.rn.bf16x2.f32 %0, %1, %2;" : "=r"(hi2) : "f"(x1), "f"(x0));
    float h0 = __uint_as_float(hi2 << 16);
    float h1 = __uint_as_float(hi2 & 0xffff0000u);
    float r0 = x0 - h0;
    float r1 = x1 - h1;
    asm("cvt.rn.bf16x2.f32 %0, %1, %2;" : "=r"(lo2) : "f"(r1), "f"(r0));
}

__device__ __forceinline__ void sts64(uint32_t addr, uint32_t a, uint32_t b) {
    asm volatile("st.shared.v2.b32 [%0], {%1, %2};"
                 :: "r"(addr), "r"(a), "r"(b) : "memory");
}

#define CP_ASYNC16(dst, src) \
    asm volatile("cp.async.cg.shared.global [%0], [%1], 16;" \
                 :: "r"(dst), "l"(src) : "memory")
#define CP_COMMIT() asm volatile("cp.async.commit_group;" ::: "memory")
#define CP_WAIT0()  asm volatile("cp.async.wait_group 0;" ::: "memory")

// ---------------------------------------------------------------------------
// Kernel 0: convert W fp32 -> bf16 hi/lo; zero g_hist
// ---------------------------------------------------------------------------
__global__ __launch_bounds__(256) void wconv_kernel(const float* __restrict__ W)
{
    int idx = blockIdx.x * 256 + threadIdx.x;      // 0 .. 32767
    float4 v = *(const float4*)(W + (size_t)idx * 4);
    uint32_t h0, l0, h1, l1;
    cvt_pair(v.x, v.y, h0, l0);
    cvt_pair(v.z, v.w, h1, l1);
    ((uint2*)g_Whi)[idx] = make_uint2(h0, h1);
    ((uint2*)g_Wlo)[idx] = make_uint2(l0, l1);
    if (idx < HBLK * NUM_EXPERTS) ((int*)g_hist)[idx] = 0;
}

// ---------------------------------------------------------------------------
// Kernel 1: HMMA split-bf16 gate GEMM, K-split x2 -> fp32 partials in gmem
// 256 threads, 8 warps (32x32 tiles), 2 CTAs/SM, ONE sync per chunk.
// ---------------------------------------------------------------------------
__global__ __launch_bounds__(256, 2) void gate_kernel(
    const float* __restrict__ X)    // [N_TOKENS, MODEL_DIM]
{
    extern __shared__ char dsm[];

    const int tid  = threadIdx.x;
    const int lane = tid & 31;
    const int w    = tid >> 5;
    const int b    = blockIdx.x >> 1;
    const int ks   = blockIdx.x & 1;
    const int t0   = b * BT;
    const int kbase = ks * KHALF;

    uint32_t smem_raw = smem_to_u32(dsm);
    const uint32_t tile0 = (smem_raw + 1023) & ~1023u;

    // Warp tile: 32 tokens x 32 experts
    const int wm = (w & 3) * 32;        // token rows
    const int wn = (w >> 2) * 32;       // expert cols

    const uint32_t a_row  = (uint32_t)(lane & 15);
    const uint32_t a_koff = (uint32_t)((lane >> 4) << 4);
    const uint32_t b_row  = (uint32_t)((lane & 7) + ((lane & 16) ? 8 : 0));
    const uint32_t b_koff = (uint32_t)((lane & 8) ? 16 : 0);

    float acc[2][4][4];
#pragma unroll
    for (int mi = 0; mi < 2; mi++)
#pragma unroll
        for (int j = 0; j < 4; j++)
#pragma unroll
            for (int q = 0; q < 4; q++) acc[mi][j][q] = 0.0f;

    // A prefetch registers: 128 rows x 16 float4 / 256 thr = 8 each
    float4 pa[8];
    const int brow = tid >> 3;          // B: 0..31 (x2 via l)
    const int bu   = tid & 7;

    // prologue: LDG A(0); cp.async B(0) into stage 0
    {
        const int k0 = kbase;
#pragma unroll
        for (int l = 0; l < 8; l++) {
            int i = l * 256 + tid;
            int row = i >> 4, q = i & 15;
            pa[l] = *(const float4*)(X + (size_t)(t0 + row) * MODEL_DIM + k0 + q * 4);
        }
#pragma unroll
        for (int l = 0; l < 2; l++) {
            int row = brow + l * 32;
            uint32_t off = SMEM_SWIZZLE_128B((uint32_t)(row * 128 + bu * 16));
            CP_ASYNC16(tile0 + B_HI_OFF + off,
                       (const char*)g_Whi + ((size_t)row * MODEL_DIM + k0) * 2 + bu * 16);
            CP_ASYNC16(tile0 + B_LO_OFF + off,
                       (const char*)g_Wlo + ((size_t)row * MODEL_DIM + k0) * 2 + bu * 16);
        }
        CP_COMMIT();
    }

    for (int c = 0; c < NCHUNK; c++) {
        const uint32_t sb  = tile0 + (uint32_t)(c & 1) * STAGE_BYTES;
        const uint32_t sbn = tile0 + (uint32_t)((c + 1) & 1) * STAGE_BYTES;

        // convert + store prefetched A chunk c into its stage
        // (safe vs other warps' MMA(c-2) on this stage: guaranteed done by sync(c-1))
#pragma unroll
        for (int l = 0; l < 8; l++) {
            int i = l * 256 + tid;
            int row = i >> 4, q = i & 15;
            uint32_t h0, l0v, h1, l1v;
            cvt_pair(pa[l].x, pa[l].y, h0, l0v);
            cvt_pair(pa[l].z, pa[l].w, h1, l1v);
            uint32_t off = SMEM_SWIZZLE_128B((uint32_t)(row * 128 + q * 8));
            sts64(sb + A_HI_OFF + off, h0, h1);
            sts64(sb + A_LO_OFF + off, l0v, l1v);
        }

        // LDG A(c+1) into regs (lands during MMA below)
        if (c + 1 < NCHUNK) {
            const int k0 = kbase + (c + 1) * KC;
#pragma unroll
            for (int l = 0; l < 8; l++) {
                int i = l * 256 + tid;
                int row = i >> 4, q = i & 15;
                pa[l] = *(const float4*)(X + (size_t)(t0 + row) * MODEL_DIM + k0 + q * 4);
            }
        }

        CP_WAIT0();          // B(c) landed
        __syncthreads();     // single sync: A(c)/B(c) visible; all MMA(c-1) done

        // cp.async B(c+1) into the opposite stage (safe post-sync: MMA(c-1) done)
        if (c + 1 < NCHUNK) {
            const int k0 = kbase + (c + 1) * KC;
#pragma unroll
            for (int l = 0; l < 2; l++) {
                int row = brow + l * 32;
                uint32_t off = SMEM_SWIZZLE_128B((uint32_t)(row * 128 + bu * 16));
                CP_ASYNC16(sbn + B_HI_OFF + off,
                           (const char*)g_Whi + ((size_t)row * MODEL_DIM + k0) * 2 + bu * 16);
                CP_ASYNC16(sbn + B_LO_OFF + off,
                           (const char*)g_Wlo + ((size_t)row * MODEL_DIM + k0) * 2 + bu * 16);
            }
            CP_COMMIT();
        }

        // compute: 4 k-steps of k16 over this chunk; bi serialized (reg pressure)
#pragma unroll
        for (int kk = 0; kk < 4; kk++) {
            uint32_t ah[2][4], al[2][4];
#pragma unroll
            for (int mi = 0; mi < 2; mi++) {
                uint32_t ro = (uint32_t)((wm + 16 * mi + a_row) * 128) + kk * 32 + a_koff;
                uint32_t sw = SMEM_SWIZZLE_128B(ro);
                ldm_x4(ah[mi], sb + A_HI_OFF + sw);
                ldm_x4(al[mi], sb + A_LO_OFF + sw);
            }
#pragma unroll
            for (int bi = 0; bi < 2; bi++) {
                uint32_t bhf[4], blf[4];
                uint32_t ro = (uint32_t)((wn + 16 * bi + b_row) * 128) + kk * 32 + b_koff;
                uint32_t sw = SMEM_SWIZZLE_128B(ro);
                ldm_x4(bhf, sb + B_HI_OFF + sw);
                ldm_x4(blf, sb + B_LO_OFF + sw);
#pragma unroll
                for (int mi = 0; mi < 2; mi++) {
#pragma unroll
                    for (int jj = 0; jj < 2; jj++) {
                        float* a = acc[mi][bi * 2 + jj];
                        mma16816(a, ah[mi], bhf[jj * 2], bhf[jj * 2 + 1]);
                        mma16816(a, ah[mi], blf[jj * 2], blf[jj * 2 + 1]);
                        mma16816(a, al[mi], bhf[jj * 2], bhf[jj * 2 + 1]);
                    }
                }
            }
        }
        // NO trailing sync: next chunk's STS targets the other stage and is
        // protected by the leading sync of the next iteration.
    }

    // Write fp32 partial logits to gmem
    float* gp = g_part[ks];
#pragma unroll
    for (int mi = 0; mi < 2; mi++) {
        int r0 = wm + 16 * mi + (lane >> 2);
#pragma unroll
        for (int j = 0; j < 4; j++) {
            int col = wn + j * 8 + 2 * (lane & 3);
            *(float2*)(gp + (size_t)(t0 + r0) * NUM_EXPERTS + col) =
                make_float2(acc[mi][j][0], acc[mi][j][1]);
            *(float2*)(gp + (size_t)(t0 + r0 + 8) * NUM_EXPERTS + col) =
                make_float2(acc[mi][j][2], acc[mi][j][3]);
        }
    }
}

// ---------------------------------------------------------------------------
// Kernel 2: warp-per-token: sum partials + softmax + top-2 + combine + hist
// 1024 blocks x 512 threads (16 warps = 16 tokens per block)
// ---------------------------------------------------------------------------
__global__ __launch_bounds__(512) void finish_kernel(float* __restrict__ out)
{
    const int tid  = threadIdx.x;
    const int lane = tid & 31;
    const int w    = tid >> 5;
    const int token = blockIdx.x * 16 + w;

    const float* p0 = g_part[0] + (size_t)token * NUM_EXPERTS;
    const float* p1 = g_part[1] + (size_t)token * NUM_EXPERTS;
    float v0 = p0[lane]      + p1[lane];
    float v1 = p0[lane + 32] + p1[lane + 32];

    // warp max -> m1
    float m = fmaxf(v0, v1);
#pragma unroll
    for (int off = 16; off > 0; off >>= 1)
        m = fmaxf(m, __shfl_xor_sync(0xffffffffu, m, off));
    const float m1 = m;

    // e1 = lowest index attaining m1 (indices 0..31 = v0 lanes, 32..63 = v1)
    unsigned bb0 = __ballot_sync(0xffffffffu, v0 == m1);
    unsigned bb1 = __ballot_sync(0xffffffffu, v1 == m1);
    const int e1 = bb0 ? (__ffs(bb0) - 1) : (32 + __ffs(bb1) - 1);

    // second max excluding e1
    float u0 = (lane == e1)      ? -INFINITY : v0;
    float u1 = (lane + 32 == e1) ? -INFINITY : v1;
    float m2 = fmaxf(u0, u1);
#pragma unroll
    for (int off = 16; off > 0; off >>= 1)
        m2 = fmaxf(m2, __shfl_xor_sync(0xffffffffu, m2, off));
    bb0 = __ballot_sync(0xffffffffu, u0 == m2);
    bb1 = __ballot_sync(0xffffffffu, u1 == m2);
    const int e2 = bb0 ? (__ffs(bb0) - 1) : (32 + __ffs(bb1) - 1);

    // softmax over 64 logits
    float ex0 = expf(v0 - m1);
    float ex1 = expf(v1 - m1);
    float s = ex0 + ex1;
#pragma unroll
    for (int off = 16; off > 0; off >>= 1)
        s += __shfl_xor_sync(0xffffffffu, s, off);
    const float inv = 1.0f / s;

    out[OFF_PROBS + (size_t)token * NUM_EXPERTS + lane]      = ex0 * inv;
    out[OFF_PROBS + (size_t)token * NUM_EXPERTS + lane + 32] = ex1 * inv;

    if (lane == 0) {
        float p1v = inv;                    // exp(m1-m1)*inv
        float p2v = expf(m2 - m1) * inv;
        float r  = expf(p2v - p1v);         // combine = softmax([p1,p2])
        float c1 = 1.0f / (1.0f + r);
        float c2 = r * c1;

        int gi = 2 * token;
        g_flat_idx[gi]     = e1;
        g_flat_idx[gi + 1] = e2;
        out[OFF_CW + gi]     = c1;
        out[OFF_CW + gi + 1] = c2;

        atomicAdd(&g_hist[token >> 7][e1], 1);
        atomicAdd(&g_hist[token >> 7][e2], 1);
    }
}

// ---------------------------------------------------------------------------
// Kernel 3: per-expert chunk-prefix + expert base offsets + input_splits
// ---------------------------------------------------------------------------
__global__ __launch_bounds__(256) void prefix_kernel(float* __restrict__ out)
{
    __shared__ int sh[HBLK * NUM_EXPERTS];   // 32KB
    __shared__ int s_cnt[NUM_EXPERTS];
    __shared__ int s_base[NUM_EXPERTS];
    const int tid = threadIdx.x;

    const int4* src = (const int4*)g_hist;
    int4* dst = (int4*)sh;
    for (int i = tid; i < HBLK * NUM_EXPERTS / 4; i += 256) dst[i] = src[i];
    __syncthreads();

    if (tid < NUM_EXPERTS) {
        int run = 0;
#pragma unroll 8
        for (int c = 0; c < HBLK; c++) run += sh[c * NUM_EXPERTS + tid];
        s_cnt[tid] = run;
    }
    __syncthreads();
    if (tid == 0) {
        int base = 0;
        for (int i = 0; i < NUM_EXPERTS; i++) { s_base[i] = base; base += s_cnt[i]; }
    }
    __syncthreads();
    if (tid < NUM_EXPERTS) {
        out[OFF_SPLITS + tid] = (float)s_cnt[tid];
        int run = s_base[tid];
#pragma unroll 8
        for (int c = 0; c < HBLK; c++) {
            g_offset[c][tid] = run;
            run += sh[c * NUM_EXPERTS + tid];
        }
    }
}

// ---------------------------------------------------------------------------
// Kernel 4: stable scatter via match_any + per-warp histograms
// 128 blocks x 256 threads (8 warps), chunk = 256 slots
// ---------------------------------------------------------------------------
__global__ __launch_bounds__(CHUNK) void scatter_kernel(float* __restrict__ out)
{
    __shared__ int whist[8][NUM_EXPERTS];
    const int tid  = threadIdx.x;
    const int lane = tid & 31;
    const int w    = tid >> 5;
    const int b    = blockIdx.x;
    const int gi   = b * CHUNK + tid;

    for (int i = tid; i < 8 * NUM_EXPERTS; i += CHUNK) ((int*)whist)[i] = 0;
    __syncthreads();

    const int me = g_flat_idx[gi];
    unsigned mask = __match_any_sync(0xffffffffu, me);
    int before = __popc(mask & ((1u << lane) - 1u));
    if (before == 0) whist[w][me] = __popc(mask);   // lowest matching lane = leader
    __syncthreads();

    int r = before;
#pragma unroll
    for (int ww = 0; ww < 8; ww++)
        if (ww < w) r += whist[ww][me];

    const int pos = g_offset[b][me] + r;
    out[OFF_TOKEN + pos] = (float)(gi >> 1);   // token index
    out[OFF_REV + gi]    = (float)pos;         // reversed ordering
}

// ---------------------------------------------------------------------------
extern "C" void kernel_launch(void* const* d_in, const int* in_sizes, int n_in,
                              void* d_out, int out_size)
{
    const float* X = (const float*)d_in[0];   // inputs [16384, 2048]
    const float* W = (const float*)d_in[1];   // wg_weight [64, 2048]
    float* out = (float*)d_out;

    cudaFuncSetAttribute(gate_kernel,
                         cudaFuncAttributeMaxDynamicSharedMemorySize, SMEM_DYN);

    wconv_kernel<<<128, 256>>>(W);
    gate_kernel<<<NGATE, 256, SMEM_DYN>>>(X);
    finish_kernel<<<N_TOKENS / 16, 512>>>(out);
    prefix_kernel<<<1, 256>>>(out);
    scatter_kernel<<<HBLK, CHUNK>>>(out);
}